// round 10
// baseline (speedup 1.0000x reference)
#include <cuda_runtime.h>
#include <cuda_fp16.h>
#include <cstdint>

#define BATCH 8
#define SEQ   2048
#define DIM   512
#define BM    128
#define BN    128
#define NT    (SEQ/BN)     // 16
#define STEPS 20           // per tile: 16 K chunks + 4 V quarters
#define TOT   (NT*STEPS)   // 320

// f16 scratch (prepass output); Q pre-scaled by log2(e)/sqrt(512)
__device__ __half g_Qh[(size_t)BATCH*SEQ*DIM];
__device__ __half g_Kh[(size_t)BATCH*SEQ*DIM];
__device__ __half g_Vh[(size_t)BATCH*SEQ*DIM];

// ---- smem layout (bytes) ----
// Q: 128 x 512 f16, row stride 1040 B
// ring: 3 slots x 16896; K chunk = 64 keys x 64 depth (stride 144 B),
//                        V qtr  = 32 keys x 256 dims (stride 528 B)
// P: 2 bufs x (128 rows x 32 keys, stride 80 B)
constexpr int SLOT    = 16896;
constexpr int OFF_Q   = 0;        // 133120
constexpr int OFF_RING= 133120;   // + 50688
constexpr int OFF_P   = 183808;   // + 20480
constexpr int OFF_SUM = 204288;   // + 2048
constexpr int SMEM_TOTAL = 206336;

__device__ __forceinline__ uint32_t smem_u32(const void* p) {
    uint32_t a;
    asm("{ .reg .u64 t; cvta.to.shared.u64 t, %1; cvt.u32.u64 %0, t; }" : "=r"(a) : "l"(p));
    return a;
}
__device__ __forceinline__ void cpa16(uint32_t dst, const void* src) {
    asm volatile("cp.async.cg.shared.global [%0], [%1], 16;" :: "r"(dst), "l"(src));
}
__device__ __forceinline__ void cpa_commit() { asm volatile("cp.async.commit_group;" ::: "memory"); }
__device__ __forceinline__ void cpa_wait1()  { asm volatile("cp.async.wait_group 1;" ::: "memory"); }
__device__ __forceinline__ void cpa_wait0()  { asm volatile("cp.async.wait_group 0;" ::: "memory"); }

__device__ __forceinline__ void ldsm4(uint32_t* r, uint32_t a) {
    asm volatile("ldmatrix.sync.aligned.m8n8.x4.shared.b16 {%0,%1,%2,%3}, [%4];"
        : "=r"(r[0]), "=r"(r[1]), "=r"(r[2]), "=r"(r[3]) : "r"(a));
}
__device__ __forceinline__ void ldsm4t(uint32_t* r, uint32_t a) {
    asm volatile("ldmatrix.sync.aligned.m8n8.x4.trans.shared.b16 {%0,%1,%2,%3}, [%4];"
        : "=r"(r[0]), "=r"(r[1]), "=r"(r[2]), "=r"(r[3]) : "r"(a));
}
__device__ __forceinline__ void mma16816(float* c, const uint32_t* a, uint32_t b0, uint32_t b1) {
    asm volatile("mma.sync.aligned.m16n8k16.row.col.f32.f16.f16.f32 "
        "{%0,%1,%2,%3}, {%4,%5,%6,%7}, {%8,%9}, {%0,%1,%2,%3};"
        : "+f"(c[0]), "+f"(c[1]), "+f"(c[2]), "+f"(c[3])
        : "r"(a[0]), "r"(a[1]), "r"(a[2]), "r"(a[3]), "r"(b0), "r"(b1));
}
__device__ __forceinline__ uint32_t packh(float f0, float f1) {
    uint32_t r;
    asm("cvt.rn.f16x2.f32 %0, %1, %2;" : "=r"(r) : "f"(f1), "f"(f0));
    return r;
}
__device__ __forceinline__ float ex2(float x) {
    float y;
    asm("ex2.approx.ftz.f32 %0, %1;" : "=f"(y) : "f"(x));
    return y;
}

// ---- prepass: f32 -> f16, Q scaled by log2(e)/sqrt(512) ----
__global__ void prep_f16(const float* __restrict__ Q,
                         const float* __restrict__ K,
                         const float* __restrict__ V) {
    size_t i4 = ((size_t)blockIdx.x * blockDim.x + threadIdx.x) * 4;
    if (i4 >= (size_t)BATCH * SEQ * DIM) return;
    int w = blockIdx.y;
    const float* src = (w == 0) ? Q : (w == 1) ? K : V;
    __half* dst = (w == 0) ? g_Qh : (w == 1) ? g_Kh : g_Vh;
    float4 f = *(const float4*)(src + i4);
    if (w == 0) {
        const float sc = 0.06376781387566735f;  // log2(e)/sqrt(512)
        f.x *= sc; f.y *= sc; f.z *= sc; f.w *= sc;
    }
    uint2 u;
    u.x = packh(f.x, f.y);
    u.y = packh(f.z, f.w);
    *(uint2*)(dst + i4) = u;
}

// ---- main kernel: BM=128, BN=128, 256 output dims per CTA (z=2) ----
__global__ __launch_bounds__(512, 1)
void attn_v6(const int* __restrict__ mask, float* __restrict__ out)
{
    extern __shared__ char smem[];
    const uint32_t sbase = smem_u32(smem);
    float* ssum = (float*)(smem + OFF_SUM);

    const int tid  = threadIdx.x;
    const int wid  = tid >> 5;
    const int lane = tid & 31;
    const int gid  = lane >> 2;
    const int tig  = lane & 3;
    const int mi   = wid & 3;    // query rows mi*32..+31
    const int ng   = wid >> 2;   // QK: keys ng*32..+31 ; PV: dims ng*64..+63
    const int khw  = ng >> 1;    // which 64-key half this warp's keys live in

    const int b  = blockIdx.y;
    const int q0 = blockIdx.x * BM;
    const int vh = blockIdx.z;   // DV half (256 dims)

    const __half* Qh = g_Qh + ((size_t)b * SEQ + q0) * DIM;
    const __half* Kh = g_Kh + (size_t)b * SEQ * DIM;
    const __half* Vh = g_Vh + (size_t)b * SEQ * DIM + vh * 256;
    const int* mb = mask + (size_t)b * SEQ;

    // stream item g: tile g/20; s = g%20: s<16 -> K chunk (cd=s>>1, kh=s&1:
    // 64 keys x 64 depth); s>=16 -> V quarter (32 keys x 256 dims). slot g%3.
    auto issue_chunk = [&](int g) {
        int tt = g / STEPS;
        int s  = g - tt * STEPS;
        uint32_t dst = sbase + OFF_RING + (uint32_t)((g % 3) * SLOT);
        if (s < 16) {
            const __half* src = Kh + (size_t)(tt * BN + (s & 1) * 64) * DIM + (s >> 1) * 64;
            int row = tid >> 3, j = tid & 7;      // 512 cps: 64 rows x 8
            cpa16(dst + row * 144 + j * 16, src + row * DIM + j * 8);
        } else {
            const __half* src = Vh + (size_t)(tt * BN + (s - 16) * 32) * DIM;
            #pragma unroll
            for (int i = 0; i < 2; i++) {         // 1024 cps: 32 rows x 32
                int g2 = tid + i * 512;
                int row = g2 >> 5, j = g2 & 31;
                cpa16(dst + row * 528 + j * 16, src + row * DIM + j * 8);
            }
        }
        cpa_commit();
    };

    // ---- prologue: Q tile + item 0 (one group), item 1 (second group) ----
    #pragma unroll
    for (int i = 0; i < 16; i++) {
        int g = tid + i * 512;                    // 8192 cps: 128 rows x 64
        int row = g >> 6, j = g & 63;
        cpa16(sbase + OFF_Q + row * 1040 + j * 16, Qh + row * DIM + j * 8);
    }
    {   // item 0 = K chunk (t0, kh0, cd0), shares group with Q
        int row = tid >> 3, j = tid & 7;
        cpa16(sbase + OFF_RING + row * 144 + j * 16, Kh + row * DIM + j * 8);
        cpa_commit();
    }
    issue_chunk(1);

    // ldmatrix bases (bytes)
    const uint32_t aQ0 = sbase + OFF_Q + (uint32_t)((mi * 32 + (lane & 15)) * 1040) + (lane >> 4) * 16;
    const uint32_t aQ1 = aQ0 + 16 * 1040;
    const uint32_t bK  = (uint32_t)(((ng & 1) * 32 + (lane & 7) + ((lane >> 4) & 1) * 8) * 144)
                       + ((lane >> 3) & 1) * 16;
    const uint32_t bV  = (uint32_t)(((lane & 7) + ((lane >> 3) & 1) * 8) * 528)
                       + (uint32_t)((ng * 64 + (lane >> 4) * 8) * 2);
    const uint32_t aPb = sbase + OFF_P + (uint32_t)((mi * 32 + (lane & 15)) * 80) + (lane >> 4) * 16;

    float ll[4] = {0.f, 0.f, 0.f, 0.f};
    float O[2][8][4];
    #pragma unroll
    for (int m = 0; m < 2; m++)
        #pragma unroll
        for (int n = 0; n < 8; n++)
            #pragma unroll
            for (int r = 0; r < 4; r++) O[m][n][r] = 0.f;

    for (int t = 0; t < NT; t++) {
        float S[2][4][4];
        #pragma unroll
        for (int m = 0; m < 2; m++)
            #pragma unroll
            for (int n = 0; n < 4; n++)
                #pragma unroll
                for (int r = 0; r < 4; r++) S[m][n][r] = 0.f;

        // ======== QK^T over 16 chunks (8 depth x 2 key-half) ========
        for (int c = 0; c < 16; c++) {
            const int g = t * STEPS + c;
            cpa_wait1();
            __syncthreads();
            if (g + 2 < TOT) issue_chunk(g + 2);

            if ((c & 1) == khw) {   // warp's keys live in this chunk
                const uint32_t kslot = sbase + OFF_RING + (uint32_t)((g % 3) * SLOT);
                const int cd = c >> 1;
                #pragma unroll
                for (int ks = 0; ks < 4; ks++) {
                    uint32_t a0[4], a1[4], b0[4], b1[4];
                    uint32_t qoff = (uint32_t)((cd * 64 + ks * 16) * 2);
                    ldsm4(a0, aQ0 + qoff);
                    ldsm4(a1, aQ1 + qoff);
                    ldsm4(b0, kslot + bK + ks * 32);
                    ldsm4(b1, kslot + bK + 16 * 144 + ks * 32);
                    mma16816(S[0][0], a0, b0[0], b0[1]);
                    mma16816(S[0][1], a0, b0[2], b0[3]);
                    mma16816(S[0][2], a0, b1[0], b1[1]);
                    mma16816(S[0][3], a0, b1[2], b1[3]);
                    mma16816(S[1][0], a1, b0[0], b0[1]);
                    mma16816(S[1][1], a1, b0[2], b0[3]);
                    mma16816(S[1][2], a1, b1[0], b1[1]);
                    mma16816(S[1][3], a1, b1[2], b1[3]);
                }
            }
        }

        // ======== softmax (static max; exp2 domain), p overwrites S ========
        const int k0 = t * BN;
        #pragma unroll
        for (int f = 0; f < 4; f++) {
            int2 m2 = *(const int2*)(mb + k0 + ng * 32 + f * 8 + 2 * tig);
            float ba = m2.x ? -1e30f : 0.f;
            float bb = m2.y ? -1e30f : 0.f;
            #pragma unroll
            for (int mt = 0; mt < 2; mt++) {
                S[mt][f][0] = ex2(S[mt][f][0] + ba);
                S[mt][f][1] = ex2(S[mt][f][1] + bb);
                S[mt][f][2] = ex2(S[mt][f][2] + ba);
                S[mt][f][3] = ex2(S[mt][f][3] + bb);
                ll[mt * 2 + 0] += S[mt][f][0] + S[mt][f][1];
                ll[mt * 2 + 1] += S[mt][f][2] + S[mt][f][3];
            }
        }

        // P quarter writer: warp-group ng==qq owns keys qq*32..+31
        auto write_P = [&](int qq) {
            uint32_t* pb = (uint32_t*)(smem + OFF_P + (qq & 1) * 10240);
            #pragma unroll
            for (int mt = 0; mt < 2; mt++)
                #pragma unroll
                for (int f = 0; f < 4; f++) {
                    int r0 = mi * 32 + mt * 16 + gid;
                    pb[r0 * 20 + f * 4 + tig]       = packh(S[mt][f][0], S[mt][f][1]);
                    pb[(r0 + 8) * 20 + f * 4 + tig] = packh(S[mt][f][2], S[mt][f][3]);
                }
        };
        if (ng == 0) write_P(0);   // published by the step-16 barrier

        // ======== P @ V over 4 key-quarter V chunks ========
        #pragma unroll
        for (int q = 0; q < 4; q++) {
            const int g = t * STEPS + 16 + q;
            if (g + 1 < TOT) cpa_wait1(); else cpa_wait0();
            __syncthreads();   // V(q) + P(q) visible; P((q+1)&1) reads done
            if (g + 2 < TOT) issue_chunk(g + 2);
            if (q < 3 && ng == q + 1) write_P(q + 1);

            const uint32_t vslot = sbase + OFF_RING + (uint32_t)((g % 3) * SLOT);
            const uint32_t aP = aPb + (uint32_t)((q & 1) * 10240);
            #pragma unroll
            for (int ks = 0; ks < 2; ks++) {
                uint32_t pa0[4], pa1[4];
                ldsm4(pa0, aP + ks * 32);
                ldsm4(pa1, aP + 16 * 80 + ks * 32);
                #pragma unroll
                for (int nt = 0; nt < 4; nt++) {
                    uint32_t vb[4];
                    ldsm4t(vb, vslot + bV + (uint32_t)(ks * 16 * 528) + nt * 32);
                    mma16816(O[0][nt * 2],     pa0, vb[0], vb[1]);
                    mma16816(O[0][nt * 2 + 1], pa0, vb[2], vb[3]);
                    mma16816(O[1][nt * 2],     pa1, vb[0], vb[1]);
                    mma16816(O[1][nt * 2 + 1], pa1, vb[2], vb[3]);
                }
            }
        }
    }

    // ======== epilogue ========
    #pragma unroll
    for (int i = 0; i < 4; i++) {
        ll[i] += __shfl_xor_sync(0xffffffffu, ll[i], 1);
        ll[i] += __shfl_xor_sync(0xffffffffu, ll[i], 2);
    }
    __syncthreads();
    if (tig == 0) {
        #pragma unroll
        for (int mt = 0; mt < 2; mt++)
            #pragma unroll
            for (int rh = 0; rh < 2; rh++)
                ssum[ng * 128 + mi * 32 + mt * 16 + rh * 8 + gid] = ll[mt * 2 + rh];
    }
    __syncthreads();

    #pragma unroll
    for (int mt = 0; mt < 2; mt++) {
        #pragma unroll
        for (int rh = 0; rh < 2; rh++) {
            int row = mi * 32 + mt * 16 + rh * 8 + gid;
            float l = ssum[row] + ssum[128 + row] + ssum[256 + row] + ssum[384 + row];
            float inv = 1.0f / l;
            float* orow = out + ((size_t)b * SEQ + q0 + row) * DIM + vh * 256 + ng * 64 + 2 * tig;
            #pragma unroll
            for (int j = 0; j < 8; j++) {
                float2 v;
                v.x = O[mt][j][rh * 2]     * inv;
                v.y = O[mt][j][rh * 2 + 1] * inv;
                *(float2*)(orow + j * 8) = v;
            }
        }
    }
}

extern "C" void kernel_launch(void* const* d_in, const int* in_sizes, int n_in,
                              void* d_out, int out_size) {
    const float* Q = (const float*)d_in[0];
    const float* K = (const float*)d_in[1];
    const float* V = (const float*)d_in[2];
    const int* mask = (const int*)d_in[3];
    float* out = (float*)d_out;

    size_t n4 = (size_t)BATCH * SEQ * DIM / 4;
    dim3 pgrid((unsigned)((n4 + 255) / 256), 3);
    prep_f16<<<pgrid, 256>>>(Q, K, V);

    cudaFuncSetAttribute(attn_v6, cudaFuncAttributeMaxDynamicSharedMemorySize, SMEM_TOTAL);
    dim3 grid(SEQ / BM, BATCH, 2);
    attn_v6<<<grid, 512, SMEM_TOTAL>>>(mask, out);
}

// round 11
// speedup vs baseline: 1.2319x; 1.2319x over previous
#include <cuda_runtime.h>
#include <cuda_fp16.h>
#include <cstdint>

#define BATCH 8
#define SEQ   2048
#define DIM   512
#define BM    128
#define BN    128
#define NT    (SEQ/BN)     // 16
#define STEPS 12           // per tile: 8 K chunks + 4 V quarters
#define TOT   (NT*STEPS)   // 192

// f16 scratch (prepass output); Q pre-scaled by log2(e)/sqrt(512)
__device__ __half g_Qh[(size_t)BATCH*SEQ*DIM];
__device__ __half g_Kh[(size_t)BATCH*SEQ*DIM];
__device__ __half g_Vh[(size_t)BATCH*SEQ*DIM];

// ---- smem layout (bytes) ----
// Q: 128 x 512 f16, row stride 1040 B
// ring: 3 slots x 18432; K chunk = 128 keys x 64 depth (stride 144 B),
//                        V qtr  = 32 keys x 256 dims (stride 528 B)
// P: 128 rows x 128 keys f16, stride 272 B
constexpr int SLOT    = 18432;
constexpr int OFF_Q   = 0;        // 133120
constexpr int OFF_RING= 133120;   // + 55296
constexpr int OFF_P   = 188416;   // + 34816
constexpr int OFF_SUM = 223232;   // + 2048
constexpr int SMEM_TOTAL = 225280;

__device__ __forceinline__ uint32_t smem_u32(const void* p) {
    uint32_t a;
    asm("{ .reg .u64 t; cvta.to.shared.u64 t, %1; cvt.u32.u64 %0, t; }" : "=r"(a) : "l"(p));
    return a;
}
__device__ __forceinline__ void cpa16(uint32_t dst, const void* src) {
    asm volatile("cp.async.cg.shared.global [%0], [%1], 16;" :: "r"(dst), "l"(src));
}
__device__ __forceinline__ void cpa_commit() { asm volatile("cp.async.commit_group;" ::: "memory"); }
__device__ __forceinline__ void cpa_wait1()  { asm volatile("cp.async.wait_group 1;" ::: "memory"); }
__device__ __forceinline__ void cpa_wait0()  { asm volatile("cp.async.wait_group 0;" ::: "memory"); }

__device__ __forceinline__ void ldsm4(uint32_t* r, uint32_t a) {
    asm volatile("ldmatrix.sync.aligned.m8n8.x4.shared.b16 {%0,%1,%2,%3}, [%4];"
        : "=r"(r[0]), "=r"(r[1]), "=r"(r[2]), "=r"(r[3]) : "r"(a));
}
__device__ __forceinline__ void ldsm4t(uint32_t* r, uint32_t a) {
    asm volatile("ldmatrix.sync.aligned.m8n8.x4.trans.shared.b16 {%0,%1,%2,%3}, [%4];"
        : "=r"(r[0]), "=r"(r[1]), "=r"(r[2]), "=r"(r[3]) : "r"(a));
}
__device__ __forceinline__ void mma16816(float* c, const uint32_t* a, uint32_t b0, uint32_t b1) {
    asm volatile("mma.sync.aligned.m16n8k16.row.col.f32.f16.f16.f32 "
        "{%0,%1,%2,%3}, {%4,%5,%6,%7}, {%8,%9}, {%0,%1,%2,%3};"
        : "+f"(c[0]), "+f"(c[1]), "+f"(c[2]), "+f"(c[3])
        : "r"(a[0]), "r"(a[1]), "r"(a[2]), "r"(a[3]), "r"(b0), "r"(b1));
}
__device__ __forceinline__ uint32_t packh(float f0, float f1) {
    uint32_t r;
    asm("cvt.rn.f16x2.f32 %0, %1, %2;" : "=r"(r) : "f"(f1), "f"(f0));
    return r;
}
__device__ __forceinline__ float ex2(float x) {
    float y;
    asm("ex2.approx.ftz.f32 %0, %1;" : "=f"(y) : "f"(x));
    return y;
}

// ---- prepass: f32 -> f16, Q scaled by log2(e)/sqrt(512) ----
__global__ void prep_f16(const float* __restrict__ Q,
                         const float* __restrict__ K,
                         const float* __restrict__ V) {
    size_t i4 = ((size_t)blockIdx.x * blockDim.x + threadIdx.x) * 4;
    if (i4 >= (size_t)BATCH * SEQ * DIM) return;
    int w = blockIdx.y;
    const float* src = (w == 0) ? Q : (w == 1) ? K : V;
    __half* dst = (w == 0) ? g_Qh : (w == 1) ? g_Kh : g_Vh;
    float4 f = *(const float4*)(src + i4);
    if (w == 0) {
        const float sc = 0.06376781387566735f;  // log2(e)/sqrt(512)
        f.x *= sc; f.y *= sc; f.z *= sc; f.w *= sc;
    }
    uint2 u;
    u.x = packh(f.x, f.y);
    u.y = packh(f.z, f.w);
    *(uint2*)(dst + i4) = u;
}

// ---- main kernel: BM=128, BN=128, 256 output dims per CTA (z=2) ----
__global__ __launch_bounds__(512, 1)
void attn_v7(const int* __restrict__ mask, float* __restrict__ out)
{
    extern __shared__ char smem[];
    const uint32_t sbase = smem_u32(smem);
    uint32_t* sP32 = (uint32_t*)(smem + OFF_P);
    float* ssum = (float*)(smem + OFF_SUM);

    const int tid  = threadIdx.x;
    const int wid  = tid >> 5;
    const int lane = tid & 31;
    const int gid  = lane >> 2;
    const int tig  = lane & 3;
    const int mi   = wid & 3;    // query rows mi*32..+31
    const int ng   = wid >> 2;   // QK: keys ng*32..+31 ; PV: dims ng*64..+63

    const int b  = blockIdx.y;
    const int q0 = blockIdx.x * BM;
    const int vh = blockIdx.z;   // DV half (256 dims)

    const __half* Qh = g_Qh + ((size_t)b * SEQ + q0) * DIM;
    const __half* Kh = g_Kh + (size_t)b * SEQ * DIM;
    const __half* Vh = g_Vh + (size_t)b * SEQ * DIM + vh * 256;
    const int* mb = mask + (size_t)b * SEQ;

    // stream item g: tile g/12; s = g%12: s<8 -> K chunk (128 keys x 64 depth),
    // s>=8 -> V quarter (32 keys x 256 dims). slot = g%3.
    auto issue_chunk = [&](int g) {
        int tt = g / STEPS;
        int s  = g - tt * STEPS;
        uint32_t dst = sbase + OFF_RING + (uint32_t)((g % 3) * SLOT);
        if (s < 8) {
            const __half* src = Kh + (size_t)(tt * BN) * DIM + s * 64;
            #pragma unroll
            for (int i = 0; i < 2; i++) {         // 1024 cps: 128 rows x 8
                int g2 = tid + i * 512;
                int row = g2 >> 3, j = g2 & 7;
                cpa16(dst + row * 144 + j * 16, src + row * DIM + j * 8);
            }
        } else {
            const __half* src = Vh + (size_t)(tt * BN + (s - 8) * 32) * DIM;
            #pragma unroll
            for (int i = 0; i < 2; i++) {         // 1024 cps: 32 rows x 32
                int g2 = tid + i * 512;
                int row = g2 >> 5, j = g2 & 31;
                cpa16(dst + row * 528 + j * 16, src + row * DIM + j * 8);
            }
        }
        cpa_commit();
    };

    // ---- prologue: Q tile + item 0 (one group), item 1 (second group) ----
    #pragma unroll
    for (int i = 0; i < 16; i++) {
        int g = tid + i * 512;                    // 8192 cps: 128 rows x 64
        int row = g >> 6, j = g & 63;
        cpa16(sbase + OFF_Q + row * 1040 + j * 16, Qh + row * DIM + j * 8);
    }
    {   // item 0 = K chunk (t0, s0), shares group with Q
        #pragma unroll
        for (int i = 0; i < 2; i++) {
            int g2 = tid + i * 512;
            int row = g2 >> 3, j = g2 & 7;
            cpa16(sbase + OFF_RING + row * 144 + j * 16, Kh + row * DIM + j * 8);
        }
        cpa_commit();
    }
    issue_chunk(1);

    // ldmatrix bases (bytes)
    const uint32_t aQ0 = sbase + OFF_Q + (uint32_t)((mi * 32 + (lane & 15)) * 1040) + (lane >> 4) * 16;
    const uint32_t aQ1 = aQ0 + 16 * 1040;
    const uint32_t bK  = (uint32_t)((ng * 32 + (lane & 7) + ((lane >> 4) & 1) * 8) * 144)
                       + ((lane >> 3) & 1) * 16;
    const uint32_t aP0 = sbase + OFF_P + (uint32_t)((mi * 32 + (lane & 15)) * 272) + (lane >> 4) * 16;
    const uint32_t aP1 = aP0 + 16 * 272;
    const uint32_t bV  = (uint32_t)(((lane & 7) + ((lane >> 3) & 1) * 8) * 528)
                       + (uint32_t)((ng * 64 + (lane >> 4) * 8) * 2);

    float ll[4] = {0.f, 0.f, 0.f, 0.f};
    float O[2][8][4];
    #pragma unroll
    for (int m = 0; m < 2; m++)
        #pragma unroll
        for (int n = 0; n < 8; n++)
            #pragma unroll
            for (int r = 0; r < 4; r++) O[m][n][r] = 0.f;

    for (int t = 0; t < NT; t++) {
        float S[2][4][4];
        #pragma unroll
        for (int m = 0; m < 2; m++)
            #pragma unroll
            for (int n = 0; n < 4; n++)
                #pragma unroll
                for (int r = 0; r < 4; r++) S[m][n][r] = 0.f;

        // ======== QK^T over 8 depth-chunks of 64 (all warps active) ========
        #pragma unroll
        for (int c = 0; c < 8; c++) {
            const int g = t * STEPS + c;
            cpa_wait1();
            __syncthreads();
            if (g + 2 < TOT) issue_chunk(g + 2);

            const uint32_t kslot = sbase + OFF_RING + (uint32_t)((g % 3) * SLOT);
            #pragma unroll
            for (int ks = 0; ks < 4; ks++) {
                uint32_t a0[4], a1[4], b0[4], b1[4];
                uint32_t qoff = (uint32_t)((c * 64 + ks * 16) * 2);
                ldsm4(a0, aQ0 + qoff);
                ldsm4(a1, aQ1 + qoff);
                ldsm4(b0, kslot + bK + ks * 32);
                ldsm4(b1, kslot + bK + 16 * 144 + ks * 32);
                mma16816(S[0][0], a0, b0[0], b0[1]);
                mma16816(S[0][1], a0, b0[2], b0[3]);
                mma16816(S[0][2], a0, b1[0], b1[1]);
                mma16816(S[0][3], a0, b1[2], b1[3]);
                mma16816(S[1][0], a1, b0[0], b0[1]);
                mma16816(S[1][1], a1, b0[2], b0[3]);
                mma16816(S[1][2], a1, b1[0], b1[1]);
                mma16816(S[1][3], a1, b1[2], b1[3]);
            }
        }

        // ======== softmax (static max; exp2 domain) -> P smem (whole) ========
        const int k0 = t * BN;
        #pragma unroll
        for (int f = 0; f < 4; f++) {
            int2 m2 = *(const int2*)(mb + k0 + ng * 32 + f * 8 + 2 * tig);
            float ba = m2.x ? -1e30f : 0.f;
            float bb = m2.y ? -1e30f : 0.f;
            #pragma unroll
            for (int mt = 0; mt < 2; mt++) {
                float p0 = ex2(S[mt][f][0] + ba);
                float p1 = ex2(S[mt][f][1] + bb);
                float p2 = ex2(S[mt][f][2] + ba);
                float p3 = ex2(S[mt][f][3] + bb);
                ll[mt * 2 + 0] += p0 + p1;
                ll[mt * 2 + 1] += p2 + p3;
                int r0 = mi * 32 + mt * 16 + gid;
                sP32[r0 * 68 + ng * 16 + f * 4 + tig] = packh(p0, p1);
                sP32[(r0 + 8) * 68 + ng * 16 + f * 4 + tig] = packh(p2, p3);
            }
        }

        // ======== P @ V over 4 key-quarter V chunks ========
        #pragma unroll
        for (int q = 0; q < 4; q++) {
            const int g = t * STEPS + 8 + q;
            if (g + 1 < TOT) cpa_wait1(); else cpa_wait0();
            __syncthreads();   // V(q) ready; P fully visible (q==0)
            if (g + 2 < TOT) issue_chunk(g + 2);

            const uint32_t vslot = sbase + OFF_RING + (uint32_t)((g % 3) * SLOT);
            #pragma unroll
            for (int ks = 0; ks < 2; ks++) {
                uint32_t pa0[4], pa1[4];
                uint32_t poff = (uint32_t)((q * 32 + ks * 16) * 2);
                ldsm4(pa0, aP0 + poff);
                ldsm4(pa1, aP1 + poff);
                #pragma unroll
                for (int nt = 0; nt < 4; nt++) {
                    uint32_t vb[4];
                    ldsm4t(vb, vslot + bV + (uint32_t)(ks * 16 * 528) + nt * 32);
                    mma16816(O[0][nt * 2],     pa0, vb[0], vb[1]);
                    mma16816(O[0][nt * 2 + 1], pa0, vb[2], vb[3]);
                    mma16816(O[1][nt * 2],     pa1, vb[0], vb[1]);
                    mma16816(O[1][nt * 2 + 1], pa1, vb[2], vb[3]);
                }
            }
        }
    }

    // ======== epilogue ========
    #pragma unroll
    for (int i = 0; i < 4; i++) {
        ll[i] += __shfl_xor_sync(0xffffffffu, ll[i], 1);
        ll[i] += __shfl_xor_sync(0xffffffffu, ll[i], 2);
    }
    __syncthreads();
    if (tig == 0) {
        #pragma unroll
        for (int mt = 0; mt < 2; mt++)
            #pragma unroll
            for (int rh = 0; rh < 2; rh++)
                ssum[ng * 128 + mi * 32 + mt * 16 + rh * 8 + gid] = ll[mt * 2 + rh];
    }
    __syncthreads();

    #pragma unroll
    for (int mt = 0; mt < 2; mt++) {
        #pragma unroll
        for (int rh = 0; rh < 2; rh++) {
            int row = mi * 32 + mt * 16 + rh * 8 + gid;
            float l = ssum[row] + ssum[128 + row] + ssum[256 + row] + ssum[384 + row];
            float inv = 1.0f / l;
            float* orow = out + ((size_t)b * SEQ + q0 + row) * DIM + vh * 256 + ng * 64 + 2 * tig;
            #pragma unroll
            for (int j = 0; j < 8; j++) {
                float2 v;
                v.x = O[mt][j][rh * 2]     * inv;
                v.y = O[mt][j][rh * 2 + 1] * inv;
                *(float2*)(orow + j * 8) = v;
            }
        }
    }
}

extern "C" void kernel_launch(void* const* d_in, const int* in_sizes, int n_in,
                              void* d_out, int out_size) {
    const float* Q = (const float*)d_in[0];
    const float* K = (const float*)d_in[1];
    const float* V = (const float*)d_in[2];
    const int* mask = (const int*)d_in[3];
    float* out = (float*)d_out;

    size_t n4 = (size_t)BATCH * SEQ * DIM / 4;
    dim3 pgrid((unsigned)((n4 + 255) / 256), 3);
    prep_f16<<<pgrid, 256>>>(Q, K, V);

    cudaFuncSetAttribute(attn_v7, cudaFuncAttributeMaxDynamicSharedMemorySize, SMEM_TOTAL);
    dim3 grid(SEQ / BM, BATCH, 2);
    attn_v7<<<grid, 512, SMEM_TOTAL>>>(mask, out);
}

// round 12
// speedup vs baseline: 2.0877x; 1.6947x over previous
#include <cuda_runtime.h>
#include <cuda_fp16.h>
#include <cstdint>

#define BATCH 8
#define SEQ   2048
#define DIM   512
#define BM    128
#define BN    128
#define STEPS 12           // per tile: 8 K chunks + 4 V quarters

// f16 scratch; K/V stored PERMUTED (unmasked keys first). Q pre-scaled.
__device__ __half g_Qh[(size_t)BATCH*SEQ*DIM];
__device__ __half g_Kh[(size_t)BATCH*SEQ*DIM];
__device__ __half g_Vh[(size_t)BATCH*SEQ*DIM];
__device__ int    g_pos[BATCH*SEQ];
__device__ int    g_cnt[BATCH];

// ---- smem layout (bytes) ----
constexpr int SLOT    = 18432;
constexpr int OFF_Q   = 0;        // 133120
constexpr int OFF_RING= 133120;   // + 55296
constexpr int OFF_P   = 188416;   // + 34816
constexpr int OFF_SUM = 223232;   // + 2048
constexpr int SMEM_TOTAL = 225280;

__device__ __forceinline__ uint32_t smem_u32(const void* p) {
    uint32_t a;
    asm("{ .reg .u64 t; cvta.to.shared.u64 t, %1; cvt.u32.u64 %0, t; }" : "=r"(a) : "l"(p));
    return a;
}
__device__ __forceinline__ void cpa16(uint32_t dst, const void* src) {
    asm volatile("cp.async.cg.shared.global [%0], [%1], 16;" :: "r"(dst), "l"(src));
}
__device__ __forceinline__ void cpa_commit() { asm volatile("cp.async.commit_group;" ::: "memory"); }
__device__ __forceinline__ void cpa_wait1()  { asm volatile("cp.async.wait_group 1;" ::: "memory"); }
__device__ __forceinline__ void cpa_wait0()  { asm volatile("cp.async.wait_group 0;" ::: "memory"); }

__device__ __forceinline__ void ldsm4(uint32_t* r, uint32_t a) {
    asm volatile("ldmatrix.sync.aligned.m8n8.x4.shared.b16 {%0,%1,%2,%3}, [%4];"
        : "=r"(r[0]), "=r"(r[1]), "=r"(r[2]), "=r"(r[3]) : "r"(a));
}
__device__ __forceinline__ void ldsm4t(uint32_t* r, uint32_t a) {
    asm volatile("ldmatrix.sync.aligned.m8n8.x4.trans.shared.b16 {%0,%1,%2,%3}, [%4];"
        : "=r"(r[0]), "=r"(r[1]), "=r"(r[2]), "=r"(r[3]) : "r"(a));
}
__device__ __forceinline__ void mma16816(float* c, const uint32_t* a, uint32_t b0, uint32_t b1) {
    asm volatile("mma.sync.aligned.m16n8k16.row.col.f32.f16.f16.f32 "
        "{%0,%1,%2,%3}, {%4,%5,%6,%7}, {%8,%9}, {%0,%1,%2,%3};"
        : "+f"(c[0]), "+f"(c[1]), "+f"(c[2]), "+f"(c[3])
        : "r"(a[0]), "r"(a[1]), "r"(a[2]), "r"(a[3]), "r"(b0), "r"(b1));
}
__device__ __forceinline__ uint32_t packh(float f0, float f1) {
    uint32_t r;
    asm("cvt.rn.f16x2.f32 %0, %1, %2;" : "=r"(r) : "f"(f1), "f"(f0));
    return r;
}
__device__ __forceinline__ float ex2(float x) {
    float y;
    asm("ex2.approx.ftz.f32 %0, %1;" : "=f"(y) : "f"(x));
    return y;
}

// ---- prepass 1: Q f32 -> f16, scaled by log2(e)/sqrt(512) ----
__global__ void prep_q(const float* __restrict__ Q) {
    size_t i4 = ((size_t)blockIdx.x * blockDim.x + threadIdx.x) * 4;
    if (i4 >= (size_t)BATCH * SEQ * DIM) return;
    const float sc = 0.06376781387566735f;
    float4 f = *(const float4*)(Q + i4);
    uint2 u;
    u.x = packh(f.x * sc, f.y * sc);
    u.y = packh(f.z * sc, f.w * sc);
    *(uint2*)(g_Qh + i4) = u;
}

// ---- prepass 2: stable partition permutation via block scan (1 block/batch) ----
__global__ void scan_mask(const int* __restrict__ mask) {
    __shared__ int s0[SEQ], s1[SEQ];
    const int b = blockIdx.x;
    const int* mb = mask + b * SEQ;
    int* cur = s0;
    int* nxt = s1;
    for (int k = threadIdx.x; k < SEQ; k += 1024)
        cur[k] = (mb[k] == 0) ? 1 : 0;          // 1 = unmasked
    __syncthreads();
    for (int off = 1; off < SEQ; off <<= 1) {
        for (int k = threadIdx.x; k < SEQ; k += 1024) {
            int v = cur[k];
            if (k >= off) v += cur[k - off];
            nxt[k] = v;
        }
        __syncthreads();
        int* tmp = cur; cur = nxt; nxt = tmp;
    }
    const int total = cur[SEQ - 1];
    for (int k = threadIdx.x; k < SEQ; k += 1024) {
        int U = cur[k];                          // inclusive unmasked count
        g_pos[b * SEQ + k] = (mb[k] == 0) ? (U - 1) : (total + k - U);
    }
    if (threadIdx.x == 0) g_cnt[b] = total;
}

// ---- prepass 3: gather-convert K/V into permuted f16 arrays (warp per key) ----
__global__ void gather_kv(const float* __restrict__ K, const float* __restrict__ V) {
    const int wid = threadIdx.x >> 5, lane = threadIdx.x & 31;
    const int k = blockIdx.x * 8 + wid;
    const int b = blockIdx.y;
    const int j = g_pos[b * SEQ + k];
    const float* ksrc = K + ((size_t)b * SEQ + k) * DIM;
    const float* vsrc = V + ((size_t)b * SEQ + k) * DIM;
    __half* kd = g_Kh + ((size_t)b * SEQ + j) * DIM;
    __half* vd = g_Vh + ((size_t)b * SEQ + j) * DIM;
    #pragma unroll
    for (int i = 0; i < 4; i++) {
        int o = lane * 4 + i * 128;
        float4 f = *(const float4*)(ksrc + o);
        uint2 u;
        u.x = packh(f.x, f.y); u.y = packh(f.z, f.w);
        *(uint2*)(kd + o) = u;
        f = *(const float4*)(vsrc + o);
        u.x = packh(f.x, f.y); u.y = packh(f.z, f.w);
        *(uint2*)(vd + o) = u;
    }
}

// ---- main kernel: BM=128, BN=128 over COMPACTED keys; 256 out dims/CTA ----
__global__ __launch_bounds__(512, 1)
void attn_v8(float* __restrict__ out)
{
    extern __shared__ char smem[];
    const uint32_t sbase = smem_u32(smem);
    uint32_t* sP32 = (uint32_t*)(smem + OFF_P);
    float* ssum = (float*)(smem + OFF_SUM);

    const int tid  = threadIdx.x;
    const int wid  = tid >> 5;
    const int lane = tid & 31;
    const int gid  = lane >> 2;
    const int tig  = lane & 3;
    const int mi   = wid & 3;
    const int ng   = wid >> 2;

    const int b  = blockIdx.y;
    const int q0 = blockIdx.x * BM;
    const int vh = blockIdx.z;

    const int cnt = g_cnt[b];
    const int nt  = (cnt + BN - 1) >> 7;   // tiles over compacted keys
    const int TOTR = nt * STEPS;

    const __half* Qh = g_Qh + ((size_t)b * SEQ + q0) * DIM;
    const __half* Kh = g_Kh + (size_t)b * SEQ * DIM;
    const __half* Vh = g_Vh + (size_t)b * SEQ * DIM + vh * 256;

    auto issue_chunk = [&](int g) {
        int tt = g / STEPS;
        int s  = g - tt * STEPS;
        uint32_t dst = sbase + OFF_RING + (uint32_t)((g % 3) * SLOT);
        if (s < 8) {
            const __half* src = Kh + (size_t)(tt * BN) * DIM + s * 64;
            #pragma unroll
            for (int i = 0; i < 2; i++) {
                int g2 = tid + i * 512;
                int row = g2 >> 3, j = g2 & 7;
                cpa16(dst + row * 144 + j * 16, src + row * DIM + j * 8);
            }
        } else {
            const __half* src = Vh + (size_t)(tt * BN + (s - 8) * 32) * DIM;
            #pragma unroll
            for (int i = 0; i < 2; i++) {
                int g2 = tid + i * 512;
                int row = g2 >> 5, j = g2 & 31;
                cpa16(dst + row * 528 + j * 16, src + row * DIM + j * 8);
            }
        }
        cpa_commit();
    };

    // ---- prologue ----
    #pragma unroll
    for (int i = 0; i < 16; i++) {
        int g = tid + i * 512;
        int row = g >> 6, j = g & 63;
        cpa16(sbase + OFF_Q + row * 1040 + j * 16, Qh + row * DIM + j * 8);
    }
    {   // item 0 shares group with Q
        #pragma unroll
        for (int i = 0; i < 2; i++) {
            int g2 = tid + i * 512;
            int row = g2 >> 3, j = g2 & 7;
            cpa16(sbase + OFF_RING + row * 144 + j * 16, Kh + row * DIM + j * 8);
        }
        cpa_commit();
    }
    issue_chunk(1);

    const uint32_t aQ0 = sbase + OFF_Q + (uint32_t)((mi * 32 + (lane & 15)) * 1040) + (lane >> 4) * 16;
    const uint32_t aQ1 = aQ0 + 16 * 1040;
    const uint32_t bK  = (uint32_t)((ng * 32 + (lane & 7) + ((lane >> 4) & 1) * 8) * 144)
                       + ((lane >> 3) & 1) * 16;
    const uint32_t aP0 = sbase + OFF_P + (uint32_t)((mi * 32 + (lane & 15)) * 272) + (lane >> 4) * 16;
    const uint32_t aP1 = aP0 + 16 * 272;
    const uint32_t bV  = (uint32_t)(((lane & 7) + ((lane >> 3) & 1) * 8) * 528)
                       + (uint32_t)((ng * 64 + (lane >> 4) * 8) * 2);

    float ll[4] = {0.f, 0.f, 0.f, 0.f};
    float O[2][8][4];
    #pragma unroll
    for (int m = 0; m < 2; m++)
        #pragma unroll
        for (int n = 0; n < 8; n++)
            #pragma unroll
            for (int r = 0; r < 4; r++) O[m][n][r] = 0.f;

    for (int t = 0; t < nt; t++) {
        float S[2][4][4];
        #pragma unroll
        for (int m = 0; m < 2; m++)
            #pragma unroll
            for (int n = 0; n < 4; n++)
                #pragma unroll
                for (int r = 0; r < 4; r++) S[m][n][r] = 0.f;

        // ======== QK^T over 8 depth-chunks ========
        #pragma unroll
        for (int c = 0; c < 8; c++) {
            const int g = t * STEPS + c;
            cpa_wait1();
            __syncthreads();
            if (g + 2 < TOTR) issue_chunk(g + 2);

            const uint32_t kslot = sbase + OFF_RING + (uint32_t)((g % 3) * SLOT);
            #pragma unroll
            for (int ks = 0; ks < 4; ks++) {
                uint32_t a0[4], a1[4], b0[4], b1[4];
                uint32_t qoff = (uint32_t)((c * 64 + ks * 16) * 2);
                ldsm4(a0, aQ0 + qoff);
                ldsm4(a1, aQ1 + qoff);
                ldsm4(b0, kslot + bK + ks * 32);
                ldsm4(b1, kslot + bK + 16 * 144 + ks * 32);
                mma16816(S[0][0], a0, b0[0], b0[1]);
                mma16816(S[0][1], a0, b0[2], b0[3]);
                mma16816(S[0][2], a0, b1[0], b1[1]);
                mma16816(S[0][3], a0, b1[2], b1[3]);
                mma16816(S[1][0], a1, b0[0], b0[1]);
                mma16816(S[1][1], a1, b0[2], b0[3]);
                mma16816(S[1][2], a1, b1[0], b1[1]);
                mma16816(S[1][3], a1, b1[2], b1[3]);
            }
        }

        // ======== softmax: bias = -inf for padding keys (idx >= cnt) ========
        const int kbase = t * BN + ng * 32 + 2 * tig;
        #pragma unroll
        for (int f = 0; f < 4; f++) {
            float ba = (kbase + f * 8)     < cnt ? 0.f : -1e30f;
            float bb = (kbase + f * 8 + 1) < cnt ? 0.f : -1e30f;
            #pragma unroll
            for (int mt = 0; mt < 2; mt++) {
                float p0 = ex2(S[mt][f][0] + ba);
                float p1 = ex2(S[mt][f][1] + bb);
                float p2 = ex2(S[mt][f][2] + ba);
                float p3 = ex2(S[mt][f][3] + bb);
                ll[mt * 2 + 0] += p0 + p1;
                ll[mt * 2 + 1] += p2 + p3;
                int r0 = mi * 32 + mt * 16 + gid;
                sP32[r0 * 68 + ng * 16 + f * 4 + tig] = packh(p0, p1);
                sP32[(r0 + 8) * 68 + ng * 16 + f * 4 + tig] = packh(p2, p3);
            }
        }

        // ======== P @ V over 4 key-quarter V chunks ========
        #pragma unroll
        for (int q = 0; q < 4; q++) {
            const int g = t * STEPS + 8 + q;
            if (g + 1 < TOTR) cpa_wait1(); else cpa_wait0();
            __syncthreads();
            if (g + 2 < TOTR) issue_chunk(g + 2);

            const uint32_t vslot = sbase + OFF_RING + (uint32_t)((g % 3) * SLOT);
            #pragma unroll
            for (int ks = 0; ks < 2; ks++) {
                uint32_t pa0[4], pa1[4];
                uint32_t poff = (uint32_t)((q * 32 + ks * 16) * 2);
                ldsm4(pa0, aP0 + poff);
                ldsm4(pa1, aP1 + poff);
                #pragma unroll
                for (int nt2 = 0; nt2 < 4; nt2++) {
                    uint32_t vb[4];
                    ldsm4t(vb, vslot + bV + (uint32_t)(ks * 16 * 528) + nt2 * 32);
                    mma16816(O[0][nt2 * 2],     pa0, vb[0], vb[1]);
                    mma16816(O[0][nt2 * 2 + 1], pa0, vb[2], vb[3]);
                    mma16816(O[1][nt2 * 2],     pa1, vb[0], vb[1]);
                    mma16816(O[1][nt2 * 2 + 1], pa1, vb[2], vb[3]);
                }
            }
        }
    }

    // ======== epilogue ========
    #pragma unroll
    for (int i = 0; i < 4; i++) {
        ll[i] += __shfl_xor_sync(0xffffffffu, ll[i], 1);
        ll[i] += __shfl_xor_sync(0xffffffffu, ll[i], 2);
    }
    __syncthreads();
    if (tig == 0) {
        #pragma unroll
        for (int mt = 0; mt < 2; mt++)
            #pragma unroll
            for (int rh = 0; rh < 2; rh++)
                ssum[ng * 128 + mi * 32 + mt * 16 + rh * 8 + gid] = ll[mt * 2 + rh];
    }
    __syncthreads();

    #pragma unroll
    for (int mt = 0; mt < 2; mt++) {
        #pragma unroll
        for (int rh = 0; rh < 2; rh++) {
            int row = mi * 32 + mt * 16 + rh * 8 + gid;
            float l = ssum[row] + ssum[128 + row] + ssum[256 + row] + ssum[384 + row];
            float inv = 1.0f / l;
            float* orow = out + ((size_t)b * SEQ + q0 + row) * DIM + vh * 256 + ng * 64 + 2 * tig;
            #pragma unroll
            for (int j = 0; j < 8; j++) {
                float2 v;
                v.x = O[mt][j][rh * 2]     * inv;
                v.y = O[mt][j][rh * 2 + 1] * inv;
                *(float2*)(orow + j * 8) = v;
            }
        }
    }
}

extern "C" void kernel_launch(void* const* d_in, const int* in_sizes, int n_in,
                              void* d_out, int out_size) {
    const float* Q = (const float*)d_in[0];
    const float* K = (const float*)d_in[1];
    const float* V = (const float*)d_in[2];
    const int* mask = (const int*)d_in[3];
    float* out = (float*)d_out;

    size_t n4 = (size_t)BATCH * SEQ * DIM / 4;
    prep_q<<<(unsigned)((n4 + 255) / 256), 256>>>(Q);
    scan_mask<<<BATCH, 1024>>>(mask);
    gather_kv<<<dim3(SEQ / 8, BATCH), 256>>>(K, V);

    cudaFuncSetAttribute(attn_v8, cudaFuncAttributeMaxDynamicSharedMemorySize, SMEM_TOTAL);
    dim3 grid(SEQ / BM, BATCH, 2);
    attn_v8<<<grid, 512, SMEM_TOTAL>>>(out);
}